// round 7
// baseline (speedup 1.0000x reference)
#include <cuda_runtime.h>
#include <cuda_bf16.h>
#include <cstdint>

#define NN 20000
#define EE 160000
#define GG 64
#define MAXD 512
#define WTOT 688128

// ---------------- scratch (interleaved bf16 hi/lo planes) -------------------
// Layout per row: granule-pairs of [16B hi (8 elems) | 16B lo (8 elems)] along K.
__device__ __align__(16) unsigned short g_x[NN * 256];        // K=128
__device__ __align__(16) unsigned short g_ag[NN * MAXD * 2];
__device__ __align__(16) unsigned short g_pA[NN * MAXD * 2];
__device__ __align__(16) unsigned short g_pB[NN * MAXD * 2];
__device__ __align__(16) unsigned short g_wl[WTOT * 2];
__device__ __align__(16) unsigned short g_wr[WTOT * 2];
__device__ int   g_rowptr[NN + 1];
__device__ int   g_fill[NN];
__device__ int   g_csr[EE];
__device__ float g_pool[GG * 256];
__device__ int   g_gs[GG];
__device__ int   g_ge[GG];

__constant__ int c_din[6]  = {128, 256, 256, 512, 512, 256};
__constant__ int c_dout[6] = {256, 256, 512, 512, 256, 256};
__constant__ int c_woff[6] = {0, 32768, 98304, 229376, 491520, 622592};

struct WPtrs { const float* w[12]; };

// ---------------- helpers ----------------------------------------------------
__device__ __forceinline__ uint32_t smem_u32(const void* p) {
    uint32_t a;
    asm("{ .reg .u64 t; cvta.to.shared.u64 t, %1; cvt.u32.u64 %0, t; }" : "=r"(a) : "l"(p));
    return a;
}
__device__ __forceinline__ uint32_t pk2(float a, float b) {  // low16=a, high16=b
    uint32_t r;
    asm("cvt.rn.bf16x2.f32 %0, %1, %2;" : "=r"(r) : "f"(b), "f"(a));
    return r;
}
__device__ __forceinline__ void split2(float v0, float v1, uint32_t& hp, uint32_t& lp) {
    hp = pk2(v0, v1);
    float h0 = __uint_as_float(hp << 16);
    float h1 = __uint_as_float(hp & 0xFFFF0000u);
    lp = pk2(v0 - h0, v1 - h1);
}
__device__ __forceinline__ void ldm4(uint32_t* r, uint32_t a) {
    asm volatile("ldmatrix.sync.aligned.m8n8.x4.shared.b16 {%0,%1,%2,%3}, [%4];"
                 : "=r"(r[0]), "=r"(r[1]), "=r"(r[2]), "=r"(r[3]) : "r"(a));
}
#define MMA_BF16(c, a, b)                                                          \
    asm volatile("mma.sync.aligned.m16n8k16.row.col.f32.bf16.bf16.f32 "            \
        "{%0,%1,%2,%3}, {%4,%5,%6,%7}, {%8,%9}, {%0,%1,%2,%3};"                     \
        : "+f"((c)[0]), "+f"((c)[1]), "+f"((c)[2]), "+f"((c)[3])                    \
        : "r"((a)[0]), "r"((a)[1]), "r"((a)[2]), "r"((a)[3]),                       \
          "r"((b)[0]), "r"((b)[1]))
#define CP16(dst, src, sz)                                                         \
    asm volatile("cp.async.cg.shared.global [%0], [%1], 16, %2;"                    \
        :: "r"(dst), "l"(src), "r"(sz) : "memory")
#define CP_COMMIT() asm volatile("cp.async.commit_group;" ::: "memory")
#define CP_WAIT1()  asm volatile("cp.async.wait_group 1;" ::: "memory")

// ---------------- fused convert: x split + weight transpose/split -----------
__global__ void k_cvtall(const float* __restrict__ x, WPtrs wp) {
    int t = threadIdx.x;
    if (blockIdx.y == 0) {
        int gi = blockIdx.x * 256 + t;  // one granule-pair (8 elems)
        if (gi < NN * 16) {
            const float4* xs = (const float4*)(x + (size_t)gi * 8);
            float4 v0 = xs[0], v1 = xs[1];
            uint32_t h0, l0, h1, l1, h2, l2, h3, l3;
            split2(v0.x, v0.y, h0, l0); split2(v0.z, v0.w, h1, l1);
            split2(v1.x, v1.y, h2, l2); split2(v1.z, v1.w, h3, l3);
            uint4* dst = (uint4*)g_x + (size_t)gi * 2;
            dst[0] = make_uint4(h0, h1, h2, h3);
            dst[1] = make_uint4(l0, l1, l2, l3);
        }
    } else {
        int id = blockIdx.y - 1, li = id >> 1, lr = id & 1;
        int K = c_din[li], Ncol = c_dout[li];
        int i = blockIdx.x * 256 + t;
        if (i < K * Ncol) {
            int k = i / Ncol, n = i % Ncol;
            const float* W = wp.w[id];
            float v = W[i];
            uint32_t hp = pk2(v, v);
            float hf = __uint_as_float(hp << 16);
            uint32_t lp = pk2(v - hf, 0.f);
            unsigned short* dst = (lr ? g_wr : g_wl) + (size_t)c_woff[li] * 2;
            size_t o = (size_t)n * K * 2 + (size_t)(k >> 3) * 16 + (k & 7);
            dst[o]     = (unsigned short)(hp & 0xFFFFu);
            dst[o + 8] = (unsigned short)(lp & 0xFFFFu);
        }
    }
}

// ---------------- fused CSR count + scan (single block) ---------------------
__global__ void k_csr(const int* __restrict__ ei) {
    extern __shared__ int sdeg[];
    __shared__ int part[1024];
    int t = threadIdx.x;
    for (int i = t; i < NN; i += 1024) sdeg[i] = 0;
    if (t < GG) { g_gs[t] = NN; g_ge[t] = 0; }
    __syncthreads();
    for (int e = t; e < EE; e += 1024) atomicAdd(&sdeg[ei[EE + e]], 1);
    __syncthreads();
    const int CH = (NN + 1023) / 1024;
    int base = t * CH, s = 0;
    for (int i = 0; i < CH; i++) { int idx = base + i; if (idx < NN) s += sdeg[idx]; }
    part[t] = s;
    __syncthreads();
    for (int off = 1; off < 1024; off <<= 1) {
        int v = (t >= off) ? part[t - off] : 0;
        __syncthreads(); part[t] += v; __syncthreads();
    }
    int run = (t == 0) ? 0 : part[t - 1];
    for (int i = 0; i < CH; i++) {
        int idx = base + i;
        if (idx < NN) { int c = sdeg[idx]; g_rowptr[idx] = run; g_fill[idx] = run; run += c; }
    }
    if (t == 1023) g_rowptr[NN] = part[1023];
}
__global__ void k_fillcsr(const int* __restrict__ ei) {
    int e = blockIdx.x * blockDim.x + threadIdx.x;
    if (e < EE) { int d = ei[EE + e]; int p = atomicAdd(&g_fill[d], 1); g_csr[p] = ei[e]; }
}

// ---------------- mean aggregation: warp = (node, 128-feat chunk) -----------
#define UNPACK_ADD(a, v)                                                     \
    do {                                                                     \
        (a)[0] += __uint_as_float((v).x << 16);                              \
        (a)[1] += __uint_as_float((v).x & 0xFFFF0000u);                      \
        (a)[2] += __uint_as_float((v).y << 16);                              \
        (a)[3] += __uint_as_float((v).y & 0xFFFF0000u);                      \
        (a)[4] += __uint_as_float((v).z << 16);                              \
        (a)[5] += __uint_as_float((v).z & 0xFFFF0000u);                      \
        (a)[6] += __uint_as_float((v).w << 16);                              \
        (a)[7] += __uint_as_float((v).w & 0xFFFF0000u);                      \
    } while (0)

__global__ void k_agg(const unsigned short* __restrict__ in,
                      unsigned short* __restrict__ out, int K) {
    int node = blockIdx.x * 8 + (threadIdx.x >> 5);
    if (node >= NN) return;
    int lane = threadIdx.x & 31;
    int rs = K >> 2;  // uint4 per row
    int cidx = blockIdx.y * 32 + lane;
    int beg = g_rowptr[node], end = g_rowptr[node + 1];
    const uint4* base = (const uint4*)in;

    float a0[8], a1[8], a2[8], a3[8];
#pragma unroll
    for (int j = 0; j < 8; j++) { a0[j] = 0.f; a1[j] = 0.f; a2[j] = 0.f; a3[j] = 0.f; }

    int e = beg;
    for (; e + 4 <= end; e += 4) {
        int s0 = g_csr[e], s1 = g_csr[e + 1], s2 = g_csr[e + 2], s3 = g_csr[e + 3];
        uint4 v0 = base[(size_t)s0 * rs + cidx];
        uint4 v1 = base[(size_t)s1 * rs + cidx];
        uint4 v2 = base[(size_t)s2 * rs + cidx];
        uint4 v3 = base[(size_t)s3 * rs + cidx];
        UNPACK_ADD(a0, v0);
        UNPACK_ADD(a1, v1);
        UNPACK_ADD(a2, v2);
        UNPACK_ADD(a3, v3);
    }
    for (; e < end; e++) {
        uint4 v = base[(size_t)g_csr[e] * rs + cidx];
        UNPACK_ADD(a0, v);
    }

    int d = end - beg;
    float inv = 1.0f / (float)(d > 0 ? d : 1);
    bool isLo = lane & 1;
    float m[8];
#pragma unroll
    for (int j = 0; j < 8; j++) {
        float s = (a0[j] + a1[j]) + (a2[j] + a3[j]);
        m[j] = (s + __shfl_xor_sync(0xFFFFFFFFu, s, 1)) * inv;
    }
    uint32_t u[4];
#pragma unroll
    for (int j = 0; j < 4; j++) {
        uint32_t hp, lp;
        split2(m[2 * j], m[2 * j + 1], hp, lp);
        u[j] = isLo ? lp : hp;
    }
    ((uint4*)out)[(size_t)node * rs + cidx] = make_uint4(u[0], u[1], u[2], u[3]);
}

// ---------------- bf16 3x-split dual GEMM, KC=64, 3-stage cp.async ----------
#define T_A 0
#define T_B 32768
#define STAGE_B 65536
#define SMEM_BYTES 196608

template <bool LEAKY>
__global__ void __launch_bounds__(256) k_gemm_tc(
    const unsigned short* __restrict__ A1, const unsigned short* __restrict__ A2,
    const unsigned short* __restrict__ W1, const unsigned short* __restrict__ W2,
    const float* __restrict__ bias, unsigned short* __restrict__ O,
    int K, int DOUT)
{
    extern __shared__ char smem[];
    const uint32_t sb = smem_u32(smem);
    const int t = threadIdx.x, lane = t & 31, wid = t >> 5;
    const int wr = wid >> 2, wc = wid & 3;
    const int m0 = blockIdx.y * 128, n0 = blockIdx.x * 128;
    const int nc = K / 64, tot = 2 * nc;  // 64-wide K chunks

    float acc[4][4][4];
#pragma unroll
    for (int i = 0; i < 4; i++)
#pragma unroll
        for (int j = 0; j < 4; j++)
#pragma unroll
            for (int k = 0; k < 4; k++) acc[i][j][k] = 0.f;

    // fill: thread -> (row = t>>1, granules gsel..gsel+7); row = 256B in smem
    const int frow = t >> 1;
    const uint32_t gsel = (uint32_t)(t & 1) * 8;
    const uint32_t rowb = (uint32_t)frow * 256;
    const uint32_t fswz = (uint32_t)(frow & 7) << 4;
    const int gra = m0 + frow;
    const uint32_t szA = (gra < NN) ? 16u : 0u;
    const size_t aoff = (size_t)(gra < NN ? gra : NN - 1) * K * 4;
    const size_t boff = (size_t)(n0 + frow) * K * 4;

    // MMA address constants
    const uint32_t lswz = (uint32_t)(lane & 7) << 4;
    const uint32_t arow = (uint32_t)(wr * 64 + (lane & 7) + ((lane >> 3) & 1) * 8);
    const uint32_t agr  = ((uint32_t)(lane >> 4)) * 32;
    const uint32_t brow = (uint32_t)(wc * 32 + (lane >> 4) * 8 + (lane & 7));
    const uint32_t bgr  = ((uint32_t)((lane >> 3) & 1)) * 32;

#define FILL(ch, stg) do {                                                         \
    const unsigned short *as_, *bs_; int kb_;                                      \
    if ((ch) < nc) { as_ = A1; bs_ = W1; kb_ = (ch) * 64; }                         \
    else           { as_ = A2; bs_ = W2; kb_ = ((ch) - nc) * 64; }                  \
    uint32_t sd_ = sb + (uint32_t)(stg) * STAGE_B + rowb;                           \
    const char* asrc = (const char*)as_ + aoff + (size_t)kb_ * 4;                   \
    const char* bsrc = (const char*)bs_ + boff + (size_t)kb_ * 4;                   \
    _Pragma("unroll")                                                               \
    for (int i_ = 0; i_ < 8; i_++) {                                                \
        uint32_t g_ = gsel + i_;                                                    \
        uint32_t off_ = (g_ * 16) ^ fswz;                                           \
        CP16(sd_ + T_A + off_, asrc + g_ * 16, szA);                                \
        CP16(sd_ + T_B + off_, bsrc + g_ * 16, 16u);                                \
    }                                                                               \
    CP_COMMIT();                                                                    \
} while (0)

    FILL(0, 0);
    FILL(1, 1);

    int stg = 0;
    for (int ch = 0; ch < tot; ch++) {
        CP_WAIT1();
        __syncthreads();
        if (ch + 2 < tot) {
            int ns = stg + 2; if (ns >= 3) ns -= 3;
            FILL(ch + 2, ns);
        } else {
            CP_COMMIT();
        }
        const uint32_t s0 = sb + (uint32_t)stg * STAGE_B;
#pragma unroll
        for (int ks = 0; ks < 4; ks++) {
            const uint32_t colb = (uint32_t)ks * 64;
            uint32_t bh[4][2], bl[4][2];
#pragma unroll
            for (int ntp = 0; ntp < 2; ntp++) {
                uint32_t rb_ = s0 + T_B + (brow + (uint32_t)ntp * 16) * 256;
                uint32_t rg[4];
                ldm4(rg, rb_ + ((colb + bgr) ^ lswz));
                bh[2 * ntp][0] = rg[0]; bh[2 * ntp][1] = rg[1];
                bh[2 * ntp + 1][0] = rg[2]; bh[2 * ntp + 1][1] = rg[3];
                ldm4(rg, rb_ + ((colb + 16 + bgr) ^ lswz));
                bl[2 * ntp][0] = rg[0]; bl[2 * ntp][1] = rg[1];
                bl[2 * ntp + 1][0] = rg[2]; bl[2 * ntp + 1][1] = rg[3];
            }
#pragma unroll
            for (int mt = 0; mt < 4; mt++) {
                uint32_t ab_ = s0 + T_A + (arow + (uint32_t)mt * 16) * 256;
                uint32_t ah[4], al[4];
                ldm4(ah, ab_ + ((colb + agr) ^ lswz));
                ldm4(al, ab_ + ((colb + 16 + agr) ^ lswz));
#pragma unroll
                for (int nt = 0; nt < 4; nt++) {
                    MMA_BF16(acc[mt][nt], ah, bh[nt]);
                    MMA_BF16(acc[mt][nt], ah, bl[nt]);
                    MMA_BF16(acc[mt][nt], al, bh[nt]);
                }
            }
        }
        stg++; if (stg >= 3) stg = 0;
    }
#undef FILL

    // epilogue: bias + optional leaky; interleaved hi/lo out
#pragma unroll
    for (int mt = 0; mt < 4; mt++) {
        int r0 = m0 + wr * 64 + mt * 16 + (lane >> 2);
        int r1 = r0 + 8;
#pragma unroll
        for (int nt = 0; nt < 4; nt++) {
            int c0 = n0 + wc * 32 + nt * 8 + (lane & 3) * 2;
            float2 b2 = *(const float2*)(bias + c0);
            float v0 = acc[mt][nt][0] + b2.x;
            float v1 = acc[mt][nt][1] + b2.y;
            float v2 = acc[mt][nt][2] + b2.x;
            float v3 = acc[mt][nt][3] + b2.y;
            if (LEAKY) {
                v0 = v0 >= 0.f ? v0 : 0.01f * v0;
                v1 = v1 >= 0.f ? v1 : 0.01f * v1;
                v2 = v2 >= 0.f ? v2 : 0.01f * v2;
                v3 = v3 >= 0.f ? v3 : 0.01f * v3;
            }
            size_t cb = (size_t)((c0 >> 3) * 32 + (c0 & 7) * 2);
            uint32_t hp, lp;
            if (r0 < NN) {
                char* p = (char*)O + (size_t)r0 * DOUT * 4 + cb;
                split2(v0, v1, hp, lp);
                *(uint32_t*)p = hp;
                *(uint32_t*)(p + 16) = lp;
            }
            if (r1 < NN) {
                char* p = (char*)O + (size_t)r1 * DOUT * 4 + cb;
                split2(v2, v3, hp, lp);
                *(uint32_t*)p = hp;
                *(uint32_t*)(p + 16) = lp;
            }
        }
    }
}

// ---------------- pool + head ------------------------------------------------
__global__ void k_bounds(const int* __restrict__ batch) {
    int n = blockIdx.x * blockDim.x + threadIdx.x;
    if (n < NN) {
        int b = batch[n];
        atomicMin(&g_gs[b], n);
        atomicMax(&g_ge[b], n + 1);
    }
}
__global__ void k_pool(const unsigned short* __restrict__ H) {
    int g = blockIdx.x, f = threadIdx.x;
    int s = g_gs[g], e = g_ge[g];
    size_t off = (size_t)(f >> 3) * 16 + (f & 7);
    float sum = 0.f;
    for (int n = s; n < e; n++) {
        const unsigned short* row = H + (size_t)n * 512;
        sum += __uint_as_float(((uint32_t)row[off]) << 16)
             + __uint_as_float(((uint32_t)row[off + 8]) << 16);
    }
    int c = e - s; if (c < 1) c = 1;
    g_pool[g * 256 + f] = sum / (float)c;
}
__global__ void k_final(const float* __restrict__ Wlin, const float* __restrict__ blin,
                        float* __restrict__ out) {
    int idx = threadIdx.x;
    if (idx >= GG * 6) return;
    int g = idx / 6, o = idx % 6;
    float s = blin[o];
#pragma unroll 8
    for (int k = 0; k < 256; k++) s += g_pool[g * 256 + k] * Wlin[k * 6 + o];
    out[idx] = s;
}

// ---------------- launcher ----------------------------------------------------
extern "C" void kernel_launch(void* const* d_in, const int* in_sizes, int n_in,
                              void* d_out, int out_size) {
    const float* x     = (const float*)d_in[0];
    const int*   ei    = (const int*)d_in[1];
    const int*   batch = (const int*)d_in[2];
    WPtrs wp;
    const float* blp[6];
    for (int l = 0; l < 6; l++) {
        wp.w[2 * l]     = (const float*)d_in[3 + 3 * l];  // Wl
        blp[l]          = (const float*)d_in[4 + 3 * l];
        wp.w[2 * l + 1] = (const float*)d_in[5 + 3 * l];  // Wr
    }
    const float* Wlin = (const float*)d_in[21];
    const float* blin = (const float*)d_in[22];
    float* out = (float*)d_out;

    unsigned short *xb, *ag, *pA, *pB, *wl, *wr;
    cudaGetSymbolAddress((void**)&xb, g_x);
    cudaGetSymbolAddress((void**)&ag, g_ag);
    cudaGetSymbolAddress((void**)&pA, g_pA);
    cudaGetSymbolAddress((void**)&pB, g_pB);
    cudaGetSymbolAddress((void**)&wl, g_wl);
    cudaGetSymbolAddress((void**)&wr, g_wr);

    cudaFuncSetAttribute(k_gemm_tc<true>,  cudaFuncAttributeMaxDynamicSharedMemorySize, SMEM_BYTES);
    cudaFuncSetAttribute(k_gemm_tc<false>, cudaFuncAttributeMaxDynamicSharedMemorySize, SMEM_BYTES);
    cudaFuncSetAttribute(k_csr, cudaFuncAttributeMaxDynamicSharedMemorySize, NN * 4);

    const int din[6]  = {128, 256, 256, 512, 512, 256};
    const int dout[6] = {256, 256, 512, 512, 256, 256};
    const int woff[6] = {0, 32768, 98304, 229376, 491520, 622592};

    // setup: convert, CSR, bounds (launch order puts gemm L1 at ncu's -s 5 slot)
    k_cvtall<<<dim3(1250, 13), 256>>>(x, wp);        // 1
    k_csr<<<1, 1024, NN * 4>>>(ei);                  // 2
    k_fillcsr<<<(EE + 255) / 256, 256>>>(ei);        // 3
    k_bounds<<<(NN + 255) / 256, 256>>>(batch);      // 4

    const unsigned short* h = xb;
    for (int l = 0; l < 6; l++) {
        unsigned short* o = (l & 1) ? pB : pA;
        dim3 agrid((NN + 7) / 8, din[l] >> 7);
        k_agg<<<agrid, 256>>>(h, ag, din[l]);        // 5 (L1)
        dim3 grid(dout[l] / 128, (NN + 127) / 128);
        if (l < 5)
            k_gemm_tc<true><<<grid, 256, SMEM_BYTES>>>(   // 6 (L1) <- profiled
                ag, h, wl + (size_t)woff[l] * 2, wr + (size_t)woff[l] * 2,
                blp[l], o, din[l], dout[l]);
        else
            k_gemm_tc<false><<<grid, 256, SMEM_BYTES>>>(
                ag, h, wl + (size_t)woff[l] * 2, wr + (size_t)woff[l] * 2,
                blp[l], o, din[l], dout[l]);
        h = o;
    }
    k_pool<<<GG, 256>>>(h);
    k_final<<<1, 384>>>(Wlin, blin, out);
}

// round 8
// speedup vs baseline: 1.2233x; 1.2233x over previous
#include <cuda_runtime.h>
#include <cuda_bf16.h>
#include <cstdint>

#define NN 20000
#define EE 160000
#define GG 64
#define MAXD 512
#define WTOT 688128

// ---------------- scratch (interleaved bf16 hi/lo planes) -------------------
// Layout per row: granule-pairs of [16B hi (8 elems) | 16B lo (8 elems)] along K.
__device__ __align__(16) unsigned short g_x[NN * 256];        // K=128
__device__ __align__(16) unsigned short g_ag[NN * MAXD * 2];
__device__ __align__(16) unsigned short g_pA[NN * MAXD * 2];
__device__ __align__(16) unsigned short g_pB[NN * MAXD * 2];
__device__ __align__(16) unsigned short g_wl[WTOT * 2];
__device__ __align__(16) unsigned short g_wr[WTOT * 2];
__device__ int   g_rowptr[NN + 1];
__device__ int   g_fill[NN];
__device__ int   g_csr[EE];
__device__ float g_pool[GG * 256];
__device__ int   g_gs[GG];
__device__ int   g_ge[GG];

__constant__ int c_din[6]  = {128, 256, 256, 512, 512, 256};
__constant__ int c_dout[6] = {256, 256, 512, 512, 256, 256};
__constant__ int c_woff[6] = {0, 32768, 98304, 229376, 491520, 622592};

struct WPtrs { const float* w[12]; };

// ---------------- helpers ----------------------------------------------------
__device__ __forceinline__ uint32_t smem_u32(const void* p) {
    uint32_t a;
    asm("{ .reg .u64 t; cvta.to.shared.u64 t, %1; cvt.u32.u64 %0, t; }" : "=r"(a) : "l"(p));
    return a;
}
__device__ __forceinline__ uint32_t pk2(float a, float b) {  // low16=a, high16=b
    uint32_t r;
    asm("cvt.rn.bf16x2.f32 %0, %1, %2;" : "=r"(r) : "f"(b), "f"(a));
    return r;
}
__device__ __forceinline__ void split2(float v0, float v1, uint32_t& hp, uint32_t& lp) {
    hp = pk2(v0, v1);
    float h0 = __uint_as_float(hp << 16);
    float h1 = __uint_as_float(hp & 0xFFFF0000u);
    lp = pk2(v0 - h0, v1 - h1);
}
__device__ __forceinline__ void ldm4(uint32_t* r, uint32_t a) {
    asm volatile("ldmatrix.sync.aligned.m8n8.x4.shared.b16 {%0,%1,%2,%3}, [%4];"
                 : "=r"(r[0]), "=r"(r[1]), "=r"(r[2]), "=r"(r[3]) : "r"(a));
}
#define MMA_BF16(c, a, b)                                                          \
    asm volatile("mma.sync.aligned.m16n8k16.row.col.f32.bf16.bf16.f32 "            \
        "{%0,%1,%2,%3}, {%4,%5,%6,%7}, {%8,%9}, {%0,%1,%2,%3};"                     \
        : "+f"((c)[0]), "+f"((c)[1]), "+f"((c)[2]), "+f"((c)[3])                    \
        : "r"((a)[0]), "r"((a)[1]), "r"((a)[2]), "r"((a)[3]),                       \
          "r"((b)[0]), "r"((b)[1]))

#define MBAR_INIT(mb, c)                                                           \
    asm volatile("mbarrier.init.shared.b64 [%0], %1;"                               \
        :: "r"((uint32_t)(mb)), "r"((uint32_t)(c)) : "memory")
#define MBAR_EXPECT(mb, bytes)                                                     \
    asm volatile("mbarrier.arrive.expect_tx.shared.b64 _, [%0], %1;"                \
        :: "r"((uint32_t)(mb)), "r"((uint32_t)(bytes)) : "memory")
#define CPBULK(dst, src, bytes, mb)                                                \
    asm volatile("cp.async.bulk.shared::cta.global.mbarrier::complete_tx::bytes "   \
        "[%0], [%1], %2, [%3];"                                                     \
        :: "r"((uint32_t)(dst)), "l"(src), "r"((uint32_t)(bytes)),                  \
           "r"((uint32_t)(mb)) : "memory")
#define MBAR_WAIT(mb, ph) do {                                                     \
    uint32_t _m = (uint32_t)(mb), _p = (uint32_t)(ph), _d;                          \
    asm volatile("{\n\t.reg .pred p;\n\t"                                           \
        "mbarrier.try_wait.parity.acquire.cta.shared::cta.b64 p, [%1], %2;\n\t"     \
        "selp.b32 %0, 1, 0, p;\n\t}" : "=r"(_d) : "r"(_m), "r"(_p) : "memory");     \
    if (!_d) {                                                                      \
        asm volatile("{\n\t.reg .pred P1;\n\tWL_%=:\n\t"                            \
            "mbarrier.try_wait.parity.acquire.cta.shared::cta.b64 P1, [%0], %1, 0x989680;\n\t" \
            "@P1 bra.uni WD_%=;\n\tbra.uni WL_%=;\n\tWD_%=:\n\t}"                    \
            :: "r"(_m), "r"(_p) : "memory");                                        \
    }                                                                               \
} while (0)

// ---------------- fused convert: x split + weight transpose/split -----------
__global__ void k_cvtall(const float* __restrict__ x, WPtrs wp) {
    int t = threadIdx.x;
    if (blockIdx.y == 0) {
        int gi = blockIdx.x * 256 + t;  // one granule-pair (8 elems)
        if (gi < NN * 16) {
            const float4* xs = (const float4*)(x + (size_t)gi * 8);
            float4 v0 = xs[0], v1 = xs[1];
            uint32_t h0, l0, h1, l1, h2, l2, h3, l3;
            split2(v0.x, v0.y, h0, l0); split2(v0.z, v0.w, h1, l1);
            split2(v1.x, v1.y, h2, l2); split2(v1.z, v1.w, h3, l3);
            uint4* dst = (uint4*)g_x + (size_t)gi * 2;
            dst[0] = make_uint4(h0, h1, h2, h3);
            dst[1] = make_uint4(l0, l1, l2, l3);
        }
    } else {
        int id = blockIdx.y - 1, li = id >> 1, lr = id & 1;
        int K = c_din[li], Ncol = c_dout[li];
        int i = blockIdx.x * 256 + t;
        if (i < K * Ncol) {
            int k = i / Ncol, n = i % Ncol;
            const float* W = wp.w[id];
            float v = W[i];
            uint32_t hp = pk2(v, v);
            float hf = __uint_as_float(hp << 16);
            uint32_t lp = pk2(v - hf, 0.f);
            unsigned short* dst = (lr ? g_wr : g_wl) + (size_t)c_woff[li] * 2;
            size_t o = (size_t)n * K * 2 + (size_t)(k >> 3) * 16 + (k & 7);
            dst[o]     = (unsigned short)(hp & 0xFFFFu);
            dst[o + 8] = (unsigned short)(lp & 0xFFFFu);
        }
    }
}

// ---------------- fused CSR count + scan (single block) ---------------------
__global__ void k_csr(const int* __restrict__ ei) {
    extern __shared__ int sdeg[];
    __shared__ int part[1024];
    int t = threadIdx.x;
    for (int i = t; i < NN; i += 1024) sdeg[i] = 0;
    if (t < GG) { g_gs[t] = NN; g_ge[t] = 0; }
    __syncthreads();
    for (int e = t; e < EE; e += 1024) atomicAdd(&sdeg[ei[EE + e]], 1);
    __syncthreads();
    const int CH = (NN + 1023) / 1024;
    int base = t * CH, s = 0;
    for (int i = 0; i < CH; i++) { int idx = base + i; if (idx < NN) s += sdeg[idx]; }
    part[t] = s;
    __syncthreads();
    for (int off = 1; off < 1024; off <<= 1) {
        int v = (t >= off) ? part[t - off] : 0;
        __syncthreads(); part[t] += v; __syncthreads();
    }
    int run = (t == 0) ? 0 : part[t - 1];
    for (int i = 0; i < CH; i++) {
        int idx = base + i;
        if (idx < NN) { int c = sdeg[idx]; g_rowptr[idx] = run; g_fill[idx] = run; run += c; }
    }
    if (t == 1023) g_rowptr[NN] = part[1023];
}
__global__ void k_fillcsr(const int* __restrict__ ei) {
    int e = blockIdx.x * blockDim.x + threadIdx.x;
    if (e < EE) { int d = ei[EE + e]; int p = atomicAdd(&g_fill[d], 1); g_csr[p] = ei[e]; }
}

// ---------------- mean aggregation: warp = (node, 128-feat chunk) -----------
#define UNPACK_ADD(a, v)                                                     \
    do {                                                                     \
        (a)[0] += __uint_as_float((v).x << 16);                              \
        (a)[1] += __uint_as_float((v).x & 0xFFFF0000u);                      \
        (a)[2] += __uint_as_float((v).y << 16);                              \
        (a)[3] += __uint_as_float((v).y & 0xFFFF0000u);                      \
        (a)[4] += __uint_as_float((v).z << 16);                              \
        (a)[5] += __uint_as_float((v).z & 0xFFFF0000u);                      \
        (a)[6] += __uint_as_float((v).w << 16);                              \
        (a)[7] += __uint_as_float((v).w & 0xFFFF0000u);                      \
    } while (0)

__global__ void k_agg(const unsigned short* __restrict__ in,
                      unsigned short* __restrict__ out, int K) {
    int node = blockIdx.x * 8 + (threadIdx.x >> 5);
    if (node >= NN) return;
    int lane = threadIdx.x & 31;
    int rs = K >> 2;  // uint4 per row
    int cidx = blockIdx.y * 32 + lane;
    int beg = g_rowptr[node], end = g_rowptr[node + 1];
    const uint4* base = (const uint4*)in;

    float a0[8], a1[8], a2[8], a3[8];
#pragma unroll
    for (int j = 0; j < 8; j++) { a0[j] = 0.f; a1[j] = 0.f; a2[j] = 0.f; a3[j] = 0.f; }

    int e = beg;
    for (; e + 4 <= end; e += 4) {
        int s0 = g_csr[e], s1 = g_csr[e + 1], s2 = g_csr[e + 2], s3 = g_csr[e + 3];
        uint4 v0 = base[(size_t)s0 * rs + cidx];
        uint4 v1 = base[(size_t)s1 * rs + cidx];
        uint4 v2 = base[(size_t)s2 * rs + cidx];
        uint4 v3 = base[(size_t)s3 * rs + cidx];
        UNPACK_ADD(a0, v0);
        UNPACK_ADD(a1, v1);
        UNPACK_ADD(a2, v2);
        UNPACK_ADD(a3, v3);
    }
    for (; e < end; e++) {
        uint4 v = base[(size_t)g_csr[e] * rs + cidx];
        UNPACK_ADD(a0, v);
    }

    int d = end - beg;
    float inv = 1.0f / (float)(d > 0 ? d : 1);
    bool isLo = lane & 1;
    float m[8];
#pragma unroll
    for (int j = 0; j < 8; j++) {
        float s = (a0[j] + a1[j]) + (a2[j] + a3[j]);
        m[j] = (s + __shfl_xor_sync(0xFFFFFFFFu, s, 1)) * inv;
    }
    uint32_t u[4];
#pragma unroll
    for (int j = 0; j < 4; j++) {
        uint32_t hp, lp;
        split2(m[2 * j], m[2 * j + 1], hp, lp);
        u[j] = isLo ? lp : hp;
    }
    ((uint4*)out)[(size_t)node * rs + cidx] = make_uint4(u[0], u[1], u[2], u[3]);
}

// ---------------- bf16 3x-split dual GEMM, cp.async.bulk 3-stage ------------
// KC=64 feats/chunk; rows padded to 272B (bank-conflict-free, no swizzle).
#define KCH 64
#define ROWB 272
#define TB_OFF 34816          // 128 rows * 272B
#define STAGE_B2 69632        // A + B halves
#define STAGE_TX 65536        // bytes actually copied per stage (256 x 256B)
#define SMEM_G 208896         // 3 stages

template <bool LEAKY>
__global__ void __launch_bounds__(256) k_gemm_tc(
    const unsigned short* __restrict__ A1, const unsigned short* __restrict__ A2,
    const unsigned short* __restrict__ W1, const unsigned short* __restrict__ W2,
    const float* __restrict__ bias, unsigned short* __restrict__ O,
    int K, int DOUT)
{
    extern __shared__ __align__(16) char smem[];
    __shared__ __align__(8) unsigned long long mbar_s[3];
    const uint32_t sb = smem_u32(smem);
    const uint32_t mb = smem_u32(mbar_s);
    const int t = threadIdx.x, lane = t & 31, wid = t >> 5;
    const int wr = wid >> 2, wc = wid & 3;
    const int m0 = blockIdx.y * 128, n0 = blockIdx.x * 128;
    const int nc = K / KCH, tot = 2 * nc;

    float acc[4][4][4];
#pragma unroll
    for (int i = 0; i < 4; i++)
#pragma unroll
        for (int j = 0; j < 4; j++)
#pragma unroll
            for (int k = 0; k < 4; k++) acc[i][j][k] = 0.f;

    // producer constants: thread t<128 -> A row t; else B row t-128 (256B/chunk)
    const bool isA = t < 128;
    int grow = isA ? (m0 + t) : (n0 + (t - 128));
    if (isA && grow >= NN) grow = NN - 1;  // OOB rows: harmless data, masked at epilogue
    const uint32_t dstoff = (isA ? 0u : (uint32_t)TB_OFF) + (uint32_t)(isA ? t : t - 128) * ROWB;
    const size_t rowbytes = (size_t)grow * K * 4;

    // MMA address constants (no swizzle; 272B row stride)
    const uint32_t arow = (uint32_t)(wr * 64 + (lane & 7) + ((lane >> 3) & 1) * 8);
    const uint32_t agr  = ((uint32_t)(lane >> 4)) * 32;
    const uint32_t brow = (uint32_t)(wc * 32 + (lane >> 4) * 8 + (lane & 7));
    const uint32_t bgr  = ((uint32_t)((lane >> 3) & 1)) * 32;

    if (t == 0) { MBAR_INIT(mb, 1); MBAR_INIT(mb + 8, 1); MBAR_INIT(mb + 16, 1); }
    __syncthreads();

#define FILLB(ch, stg) do {                                                        \
    const unsigned short *as_, *bs_; int kb_;                                      \
    if ((ch) < nc) { as_ = A1; bs_ = W1; kb_ = (ch) * KCH; }                        \
    else           { as_ = A2; bs_ = W2; kb_ = ((ch) - nc) * KCH; }                 \
    if (t == 0) MBAR_EXPECT(mb + (stg) * 8, STAGE_TX);                              \
    const char* src_ = (const char*)(isA ? as_ : bs_) + rowbytes + (size_t)kb_ * 4; \
    CPBULK(sb + (uint32_t)(stg) * STAGE_B2 + dstoff, src_, 256u, mb + (stg) * 8);   \
} while (0)

    FILLB(0, 0);
    FILLB(1, 1);
    FILLB(2, 2);

    for (int ch = 0; ch < tot; ch++) {
        const int stg = ch % 3;
        const int par = (ch / 3) & 1;
        MBAR_WAIT(mb + stg * 8, par);

        const uint32_t s0 = sb + (uint32_t)stg * STAGE_B2;
#pragma unroll
        for (int ks = 0; ks < 4; ks++) {
            const uint32_t colb = (uint32_t)ks * 64;
            uint32_t bh[4][2], bl[4][2];
#pragma unroll
            for (int ntp = 0; ntp < 2; ntp++) {
                uint32_t rb_ = s0 + TB_OFF + (brow + (uint32_t)ntp * 16) * ROWB;
                uint32_t rg[4];
                ldm4(rg, rb_ + colb + bgr);
                bh[2 * ntp][0] = rg[0]; bh[2 * ntp][1] = rg[1];
                bh[2 * ntp + 1][0] = rg[2]; bh[2 * ntp + 1][1] = rg[3];
                ldm4(rg, rb_ + colb + 16 + bgr);
                bl[2 * ntp][0] = rg[0]; bl[2 * ntp][1] = rg[1];
                bl[2 * ntp + 1][0] = rg[2]; bl[2 * ntp + 1][1] = rg[3];
            }
#pragma unroll
            for (int mt = 0; mt < 4; mt++) {
                uint32_t ab_ = s0 + (arow + (uint32_t)mt * 16) * ROWB;
                uint32_t ah[4], al[4];
                ldm4(ah, ab_ + colb + agr);
                ldm4(al, ab_ + colb + 16 + agr);
#pragma unroll
                for (int nt = 0; nt < 4; nt++) {
                    MMA_BF16(acc[mt][nt], ah, bh[nt]);
                    MMA_BF16(acc[mt][nt], ah, bl[nt]);
                    MMA_BF16(acc[mt][nt], al, bh[nt]);
                }
            }
        }
        __syncthreads();  // all warps done reading stage stg
        if (ch + 3 < tot) FILLB(ch + 3, stg);
    }
#undef FILLB

    // epilogue: bias + optional leaky; interleaved hi/lo out
#pragma unroll
    for (int mt = 0; mt < 4; mt++) {
        int r0 = m0 + wr * 64 + mt * 16 + (lane >> 2);
        int r1 = r0 + 8;
#pragma unroll
        for (int nt = 0; nt < 4; nt++) {
            int c0 = n0 + wc * 32 + nt * 8 + (lane & 3) * 2;
            float2 b2 = *(const float2*)(bias + c0);
            float v0 = acc[mt][nt][0] + b2.x;
            float v1 = acc[mt][nt][1] + b2.y;
            float v2 = acc[mt][nt][2] + b2.x;
            float v3 = acc[mt][nt][3] + b2.y;
            if (LEAKY) {
                v0 = v0 >= 0.f ? v0 : 0.01f * v0;
                v1 = v1 >= 0.f ? v1 : 0.01f * v1;
                v2 = v2 >= 0.f ? v2 : 0.01f * v2;
                v3 = v3 >= 0.f ? v3 : 0.01f * v3;
            }
            size_t cb = (size_t)((c0 >> 3) * 32 + (c0 & 7) * 2);
            uint32_t hp, lp;
            if (r0 < NN) {
                char* p = (char*)O + (size_t)r0 * DOUT * 4 + cb;
                split2(v0, v1, hp, lp);
                *(uint32_t*)p = hp;
                *(uint32_t*)(p + 16) = lp;
            }
            if (r1 < NN) {
                char* p = (char*)O + (size_t)r1 * DOUT * 4 + cb;
                split2(v2, v3, hp, lp);
                *(uint32_t*)p = hp;
                *(uint32_t*)(p + 16) = lp;
            }
        }
    }
}

// ---------------- pool + head ------------------------------------------------
__global__ void k_bounds(const int* __restrict__ batch) {
    int n = blockIdx.x * blockDim.x + threadIdx.x;
    if (n < NN) {
        int b = batch[n];
        atomicMin(&g_gs[b], n);
        atomicMax(&g_ge[b], n + 1);
    }
}
__global__ void k_pool(const unsigned short* __restrict__ H) {
    int g = blockIdx.x, f = threadIdx.x;
    int s = g_gs[g], e = g_ge[g];
    size_t off = (size_t)(f >> 3) * 16 + (f & 7);
    float sum = 0.f;
    for (int n = s; n < e; n++) {
        const unsigned short* row = H + (size_t)n * 512;
        sum += __uint_as_float(((uint32_t)row[off]) << 16)
             + __uint_as_float(((uint32_t)row[off + 8]) << 16);
    }
    int c = e - s; if (c < 1) c = 1;
    g_pool[g * 256 + f] = sum / (float)c;
}
__global__ void k_final(const float* __restrict__ Wlin, const float* __restrict__ blin,
                        float* __restrict__ out) {
    int idx = threadIdx.x;
    if (idx >= GG * 6) return;
    int g = idx / 6, o = idx % 6;
    float s = blin[o];
#pragma unroll 8
    for (int k = 0; k < 256; k++) s += g_pool[g * 256 + k] * Wlin[k * 6 + o];
    out[idx] = s;
}

// ---------------- launcher ----------------------------------------------------
extern "C" void kernel_launch(void* const* d_in, const int* in_sizes, int n_in,
                              void* d_out, int out_size) {
    const float* x     = (const float*)d_in[0];
    const int*   ei    = (const int*)d_in[1];
    const int*   batch = (const int*)d_in[2];
    WPtrs wp;
    const float* blp[6];
    for (int l = 0; l < 6; l++) {
        wp.w[2 * l]     = (const float*)d_in[3 + 3 * l];  // Wl
        blp[l]          = (const float*)d_in[4 + 3 * l];
        wp.w[2 * l + 1] = (const float*)d_in[5 + 3 * l];  // Wr
    }
    const float* Wlin = (const float*)d_in[21];
    const float* blin = (const float*)d_in[22];
    float* out = (float*)d_out;

    unsigned short *xb, *ag, *pA, *pB, *wl, *wr;
    cudaGetSymbolAddress((void**)&xb, g_x);
    cudaGetSymbolAddress((void**)&ag, g_ag);
    cudaGetSymbolAddress((void**)&pA, g_pA);
    cudaGetSymbolAddress((void**)&pB, g_pB);
    cudaGetSymbolAddress((void**)&wl, g_wl);
    cudaGetSymbolAddress((void**)&wr, g_wr);

    cudaFuncSetAttribute(k_gemm_tc<true>,  cudaFuncAttributeMaxDynamicSharedMemorySize, SMEM_G);
    cudaFuncSetAttribute(k_gemm_tc<false>, cudaFuncAttributeMaxDynamicSharedMemorySize, SMEM_G);
    cudaFuncSetAttribute(k_csr, cudaFuncAttributeMaxDynamicSharedMemorySize, NN * 4);

    const int din[6]  = {128, 256, 256, 512, 512, 256};
    const int dout[6] = {256, 256, 512, 512, 256, 256};
    const int woff[6] = {0, 32768, 98304, 229376, 491520, 622592};

    // setup
    k_cvtall<<<dim3(1250, 13), 256>>>(x, wp);
    k_csr<<<1, 1024, NN * 4>>>(ei);
    k_fillcsr<<<(EE + 255) / 256, 256>>>(ei);
    k_bounds<<<(NN + 255) / 256, 256>>>(batch);

    const unsigned short* h = xb;
    for (int l = 0; l < 6; l++) {
        unsigned short* o = (l & 1) ? pB : pA;
        dim3 agrid((NN + 7) / 8, din[l] >> 7);
        k_agg<<<agrid, 256>>>(h, ag, din[l]);
        dim3 grid(dout[l] / 128, (NN + 127) / 128);
        if (l < 5)
            k_gemm_tc<true><<<grid, 256, SMEM_G>>>(
                ag, h, wl + (size_t)woff[l] * 2, wr + (size_t)woff[l] * 2,
                blp[l], o, din[l], dout[l]);
        else
            k_gemm_tc<false><<<grid, 256, SMEM_G>>>(
                ag, h, wl + (size_t)woff[l] * 2, wr + (size_t)woff[l] * 2,
                blp[l], o, din[l], dout[l]);
        h = o;
    }
    k_pool<<<GG, 256>>>(h);
    k_final<<<1, 384>>>(Wlin, blin, out);
}

// round 9
// speedup vs baseline: 1.3327x; 1.0894x over previous
#include <cuda_runtime.h>
#include <cuda_bf16.h>
#include <cstdint>

#define NN 20000
#define EE 160000
#define GG 64
#define MAXD 512
#define WTOT 688128

// ---------------- scratch (separate bf16 hi/lo planes — proven R4 layout) ---
__device__ __align__(16) unsigned short g_xh[NN * 128];
__device__ __align__(16) unsigned short g_xl[NN * 128];
__device__ __align__(16) unsigned short g_agh[NN * MAXD];
__device__ __align__(16) unsigned short g_agl[NN * MAXD];
__device__ __align__(16) unsigned short g_Ah[NN * MAXD];
__device__ __align__(16) unsigned short g_Al[NN * MAXD];
__device__ __align__(16) unsigned short g_Bh[NN * MAXD];
__device__ __align__(16) unsigned short g_Bl[NN * MAXD];
__device__ __align__(16) unsigned short g_wlh[WTOT];
__device__ __align__(16) unsigned short g_wll[WTOT];
__device__ __align__(16) unsigned short g_wrh[WTOT];
__device__ __align__(16) unsigned short g_wrl[WTOT];
__device__ int   g_deg[NN];          // zero at module load; k_scan re-zeroes
__device__ int   g_rowptr[NN + 1];
__device__ int   g_fill[NN];
__device__ int   g_csr[EE];
__device__ float g_pool[GG * 256];

__constant__ int c_din[6]  = {128, 256, 256, 512, 512, 256};
__constant__ int c_dout[6] = {256, 256, 512, 512, 256, 256};
__constant__ int c_woff[6] = {0, 32768, 98304, 229376, 491520, 622592};

struct WPtrs { const float* w[12]; };

// ---------------- helpers ----------------------------------------------------
__device__ __forceinline__ uint32_t smem_u32(const void* p) {
    uint32_t a;
    asm("{ .reg .u64 t; cvta.to.shared.u64 t, %1; cvt.u32.u64 %0, t; }" : "=r"(a) : "l"(p));
    return a;
}
__device__ __forceinline__ uint32_t pk2(float a, float b) {  // low16=a, high16=b
    uint32_t r;
    asm("cvt.rn.bf16x2.f32 %0, %1, %2;" : "=r"(r) : "f"(b), "f"(a));
    return r;
}
__device__ __forceinline__ void split2(float v0, float v1, uint32_t& hp, uint32_t& lp) {
    hp = pk2(v0, v1);
    float h0 = __uint_as_float(hp << 16);
    float h1 = __uint_as_float(hp & 0xFFFF0000u);
    lp = pk2(v0 - h0, v1 - h1);
}
__device__ __forceinline__ void ldm4(uint32_t* r, uint32_t a) {
    asm volatile("ldmatrix.sync.aligned.m8n8.x4.shared.b16 {%0,%1,%2,%3}, [%4];"
                 : "=r"(r[0]), "=r"(r[1]), "=r"(r[2]), "=r"(r[3]) : "r"(a));
}
__device__ __forceinline__ void ldm2(uint32_t* r, uint32_t a) {
    asm volatile("ldmatrix.sync.aligned.m8n8.x2.shared.b16 {%0,%1}, [%2];"
                 : "=r"(r[0]), "=r"(r[1]) : "r"(a));
}
#define MMA_BF16(c, a, b)                                                          \
    asm volatile("mma.sync.aligned.m16n8k16.row.col.f32.bf16.bf16.f32 "            \
        "{%0,%1,%2,%3}, {%4,%5,%6,%7}, {%8,%9}, {%0,%1,%2,%3};"                     \
        : "+f"((c)[0]), "+f"((c)[1]), "+f"((c)[2]), "+f"((c)[3])                    \
        : "r"((a)[0]), "r"((a)[1]), "r"((a)[2]), "r"((a)[3]),                       \
          "r"((b)[0]), "r"((b)[1]))
#define CP16(dst, src, sz)                                                         \
    asm volatile("cp.async.cg.shared.global [%0], [%1], 16, %2;"                    \
        :: "r"(dst), "l"(src), "r"(sz) : "memory")
#define CP_COMMIT() asm volatile("cp.async.commit_group;" ::: "memory")
#define CP_WAIT1()  asm volatile("cp.async.wait_group 1;" ::: "memory")
#define CP_WAIT0()  asm volatile("cp.async.wait_group 0;" ::: "memory")

// ---------------- fused convert: x split + weight transpose/split -----------
__global__ void k_cvtall(const float* __restrict__ x, WPtrs wp) {
    int t = threadIdx.x;
    if (blockIdx.y == 0) {
        int gi = blockIdx.x * 256 + t;  // one 8-elem granule
        if (gi < NN * 16) {
            const float4* xs = (const float4*)(x + (size_t)gi * 8);
            float4 v0 = xs[0], v1 = xs[1];
            uint32_t h0, l0, h1, l1, h2, l2, h3, l3;
            split2(v0.x, v0.y, h0, l0); split2(v0.z, v0.w, h1, l1);
            split2(v1.x, v1.y, h2, l2); split2(v1.z, v1.w, h3, l3);
            ((uint4*)g_xh)[gi] = make_uint4(h0, h1, h2, h3);
            ((uint4*)g_xl)[gi] = make_uint4(l0, l1, l2, l3);
        }
    } else {
        int id = blockIdx.y - 1, li = id >> 1, lr = id & 1;
        int K = c_din[li], Ncol = c_dout[li];
        int i = blockIdx.x * 256 + t;
        if (i < K * Ncol) {
            int k = i / Ncol, n = i % Ncol;
            float v = wp.w[id][i];
            uint32_t hp = pk2(v, v);
            float hf = __uint_as_float(hp << 16);
            uint32_t lp = pk2(v - hf, 0.f);
            unsigned short* wh = (lr ? g_wrh : g_wlh) + c_woff[li];
            unsigned short* wl = (lr ? g_wrl : g_wll) + c_woff[li];
            wh[(size_t)n * K + k] = (unsigned short)(hp & 0xFFFFu);
            wl[(size_t)n * K + k] = (unsigned short)(lp & 0xFFFFu);
        }
    }
}

// ---------------- CSR build (parallel; scan self-zeroes g_deg) --------------
__global__ void k_count(const int* __restrict__ ei) {
    int e = blockIdx.x * blockDim.x + threadIdx.x;
    if (e < EE) atomicAdd(&g_deg[ei[EE + e]], 1);
}
__global__ void k_scan() {
    __shared__ int part[1024];
    int t = threadIdx.x;
    const int CH = (NN + 1023) / 1024;
    int base = t * CH, s = 0;
    for (int i = 0; i < CH; i++) { int idx = base + i; if (idx < NN) s += g_deg[idx]; }
    part[t] = s;
    __syncthreads();
    for (int off = 1; off < 1024; off <<= 1) {
        int v = (t >= off) ? part[t - off] : 0;
        __syncthreads(); part[t] += v; __syncthreads();
    }
    int run = (t == 0) ? 0 : part[t - 1];
    for (int i = 0; i < CH; i++) {
        int idx = base + i;
        if (idx < NN) {
            int c = g_deg[idx];
            g_rowptr[idx] = run; g_fill[idx] = run; run += c;
            g_deg[idx] = 0;  // reset for next graph replay (deterministic)
        }
    }
    if (t == 1023) g_rowptr[NN] = part[1023];
}
__global__ void k_fillcsr(const int* __restrict__ ei) {
    int e = blockIdx.x * blockDim.x + threadIdx.x;
    if (e < EE) { int d = ei[EE + e]; int p = atomicAdd(&g_fill[d], 1); g_csr[p] = ei[e]; }
}

// ---------------- mean aggregation: warp=(node, 128-feat chunk), 4-unroll ---
__device__ __forceinline__ void acc_u2(float* a, uint2 h, uint2 l) {
    a[0] += __uint_as_float(h.x << 16)         + __uint_as_float(l.x << 16);
    a[1] += __uint_as_float(h.x & 0xFFFF0000u) + __uint_as_float(l.x & 0xFFFF0000u);
    a[2] += __uint_as_float(h.y << 16)         + __uint_as_float(l.y << 16);
    a[3] += __uint_as_float(h.y & 0xFFFF0000u) + __uint_as_float(l.y & 0xFFFF0000u);
}

__global__ void k_agg(const unsigned short* __restrict__ ph, const unsigned short* __restrict__ pl,
                      unsigned short* __restrict__ oh, unsigned short* __restrict__ ol, int K) {
    int node = blockIdx.x * 8 + (threadIdx.x >> 5);
    if (node >= NN) return;
    int lane = threadIdx.x & 31;
    int rs = K >> 2;                       // uint2 elems per row
    int cidx = blockIdx.y * 32 + lane;     // this warp's feature chunk
    int beg = g_rowptr[node], end = g_rowptr[node + 1];
    const uint2* bh = (const uint2*)ph;
    const uint2* bl = (const uint2*)pl;

    float a0[4], a1[4], a2[4], a3[4];
#pragma unroll
    for (int j = 0; j < 4; j++) { a0[j] = 0.f; a1[j] = 0.f; a2[j] = 0.f; a3[j] = 0.f; }

    int e = beg;
    for (; e + 4 <= end; e += 4) {
        int s0 = g_csr[e], s1 = g_csr[e + 1], s2 = g_csr[e + 2], s3 = g_csr[e + 3];
        uint2 h0 = bh[(size_t)s0 * rs + cidx], l0 = bl[(size_t)s0 * rs + cidx];
        uint2 h1 = bh[(size_t)s1 * rs + cidx], l1 = bl[(size_t)s1 * rs + cidx];
        uint2 h2 = bh[(size_t)s2 * rs + cidx], l2 = bl[(size_t)s2 * rs + cidx];
        uint2 h3 = bh[(size_t)s3 * rs + cidx], l3 = bl[(size_t)s3 * rs + cidx];
        acc_u2(a0, h0, l0); acc_u2(a1, h1, l1); acc_u2(a2, h2, l2); acc_u2(a3, h3, l3);
    }
    for (; e < end; e++) {
        int s = g_csr[e];
        acc_u2(a0, bh[(size_t)s * rs + cidx], bl[(size_t)s * rs + cidx]);
    }

    int d = end - beg;
    float inv = 1.0f / (float)(d > 0 ? d : 1);
    float m[4];
#pragma unroll
    for (int j = 0; j < 4; j++) m[j] = ((a0[j] + a1[j]) + (a2[j] + a3[j])) * inv;
    uint32_t hp0, lp0, hp1, lp1;
    split2(m[0], m[1], hp0, lp0);
    split2(m[2], m[3], hp1, lp1);
    ((uint2*)oh)[(size_t)node * rs + cidx] = make_uint2(hp0, hp1);
    ((uint2*)ol)[(size_t)node * rs + cidx] = make_uint2(lp0, lp1);
}

// ---------------- bf16 3x-split dual GEMM (R4 proven: KC=32, 2-stage) -------
#define T_AH 0
#define T_AL 8192
#define T_BH 16384
#define T_BL 24576
#define STAGE_B 32768
#define SMEM_BYTES 65536

template <bool LEAKY>
__global__ void __launch_bounds__(256) k_gemm_tc(
    const unsigned short* __restrict__ a1h, const unsigned short* __restrict__ a1l,
    const unsigned short* __restrict__ a2h, const unsigned short* __restrict__ a2l,
    const unsigned short* __restrict__ b1h, const unsigned short* __restrict__ b1l,
    const unsigned short* __restrict__ b2h, const unsigned short* __restrict__ b2l,
    const float* __restrict__ bias,
    unsigned short* __restrict__ Oh, unsigned short* __restrict__ Ol,
    int K, int DOUT)
{
    extern __shared__ char smem[];
    const uint32_t sb = smem_u32(smem);
    const int t = threadIdx.x, lane = t & 31, wid = t >> 5;
    const int wr = wid >> 2, wc = wid & 3;
    const int m0 = blockIdx.y * 128, n0 = blockIdx.x * 128;
    const int nc = K / 32, tot = 2 * nc;

    float acc[4][4][4];
#pragma unroll
    for (int i = 0; i < 4; i++)
#pragma unroll
        for (int j = 0; j < 4; j++)
#pragma unroll
            for (int k = 0; k < 4; k++) acc[i][j][k] = 0.f;

    // fill constants: thread handles granule g of rows row0 and row0+64 per tile
    const int row0 = t >> 2;
    const int g = t & 3;
    const uint32_t d0 = (uint32_t)row0 * 64 + (((uint32_t)g * 16) ^ (((uint32_t)row0 & 6) << 3));
    const uint32_t d1 = d0 + 4096;  // row0+64: same swizzle bits
    const int gr0 = m0 + row0, gr1 = m0 + row0 + 64;
    const uint32_t sz0 = (gr0 < NN) ? 16u : 0u;
    const uint32_t sz1 = (gr1 < NN) ? 16u : 0u;
    const size_t aoff0 = (size_t)(gr0 < NN ? gr0 : NN - 1) * K + g * 8;
    const size_t aoff1 = (size_t)(gr1 < NN ? gr1 : NN - 1) * K + g * 8;
    const size_t boff0 = (size_t)(n0 + row0) * K + g * 8;
    const size_t boff1 = (size_t)(n0 + row0 + 64) * K + g * 8;

    // MMA fragment address constants
    const uint32_t fxor = ((uint32_t)(lane & 6)) << 3;
    const int ra = wr * 64 + (lane & 7) + ((lane >> 3) & 1) * 8;
    const uint32_t achk = ((uint32_t)(lane >> 4)) * 16;
    const int rb = wc * 32 + (lane & 7);
    const uint32_t bchk = ((uint32_t)((lane >> 3) & 1)) * 16;

#define FILL(ch, stg) do {                                                         \
    const unsigned short *ah_, *al_, *bh_, *bl_; int kb_;                          \
    if ((ch) < nc) { ah_ = a1h; al_ = a1l; bh_ = b1h; bl_ = b1l; kb_ = (ch) * 32; } \
    else           { ah_ = a2h; al_ = a2l; bh_ = b2h; bl_ = b2l; kb_ = ((ch) - nc) * 32; } \
    uint32_t s0_ = sb + (stg) * STAGE_B;                                           \
    CP16(s0_ + T_AH + d0, ah_ + aoff0 + kb_, sz0);                                 \
    CP16(s0_ + T_AH + d1, ah_ + aoff1 + kb_, sz1);                                 \
    CP16(s0_ + T_AL + d0, al_ + aoff0 + kb_, sz0);                                 \
    CP16(s0_ + T_AL + d1, al_ + aoff1 + kb_, sz1);                                 \
    CP16(s0_ + T_BH + d0, bh_ + boff0 + kb_, 16u);                                 \
    CP16(s0_ + T_BH + d1, bh_ + boff1 + kb_, 16u);                                 \
    CP16(s0_ + T_BL + d0, bl_ + boff0 + kb_, 16u);                                 \
    CP16(s0_ + T_BL + d1, bl_ + boff1 + kb_, 16u);                                 \
    CP_COMMIT();                                                                   \
} while (0)

    FILL(0, 0);

    for (int ch = 0; ch < tot; ch++) {
        __syncthreads();  // prior MMA reads done before overwriting other stage
        if (ch + 1 < tot) { FILL(ch + 1, (ch + 1) & 1); CP_WAIT1(); }
        else              { CP_WAIT0(); }
        __syncthreads();

        const uint32_t s0 = sb + (ch & 1) * STAGE_B;
#pragma unroll
        for (int ks = 0; ks < 2; ks++) {
            uint32_t ah[4][4], al[4][4], bh[4][2], bl[4][2];
#pragma unroll
            for (int mt = 0; mt < 4; mt++) {
                uint32_t base = sb + (ch & 1) * STAGE_B + (uint32_t)(ra + mt * 16) * 64;
                ldm4(ah[mt], base + T_AH + (((uint32_t)(ks * 32) + achk) ^ fxor));
                ldm4(al[mt], base + T_AL + (((uint32_t)(ks * 32) + achk) ^ fxor));
            }
#pragma unroll
            for (int nt = 0; nt < 4; nt++) {
                uint32_t base = s0 + (uint32_t)(rb + nt * 8) * 64;
                ldm2(bh[nt], base + T_BH + (((uint32_t)(ks * 32) + bchk) ^ fxor));
                ldm2(bl[nt], base + T_BL + (((uint32_t)(ks * 32) + bchk) ^ fxor));
            }
#pragma unroll
            for (int mt = 0; mt < 4; mt++)
#pragma unroll
                for (int nt = 0; nt < 4; nt++) {
                    MMA_BF16(acc[mt][nt], ah[mt], bh[nt]);
                    MMA_BF16(acc[mt][nt], ah[mt], bl[nt]);
                    MMA_BF16(acc[mt][nt], al[mt], bh[nt]);
                }
        }
    }
#undef FILL

    // epilogue: bias + optional leaky; write hi/lo planes
#pragma unroll
    for (int mt = 0; mt < 4; mt++) {
        int r0 = m0 + wr * 64 + mt * 16 + (lane >> 2);
        int r1 = r0 + 8;
#pragma unroll
        for (int nt = 0; nt < 4; nt++) {
            int c0 = n0 + wc * 32 + nt * 8 + (lane & 3) * 2;
            float2 b2 = *(const float2*)(bias + c0);
            float v0 = acc[mt][nt][0] + b2.x;
            float v1 = acc[mt][nt][1] + b2.y;
            float v2 = acc[mt][nt][2] + b2.x;
            float v3 = acc[mt][nt][3] + b2.y;
            if (LEAKY) {
                v0 = v0 >= 0.f ? v0 : 0.01f * v0;
                v1 = v1 >= 0.f ? v1 : 0.01f * v1;
                v2 = v2 >= 0.f ? v2 : 0.01f * v2;
                v3 = v3 >= 0.f ? v3 : 0.01f * v3;
            }
            uint32_t hp, lp;
            if (r0 < NN) {
                split2(v0, v1, hp, lp);
                *(uint32_t*)(Oh + (size_t)r0 * DOUT + c0) = hp;
                *(uint32_t*)(Ol + (size_t)r0 * DOUT + c0) = lp;
            }
            if (r1 < NN) {
                split2(v2, v3, hp, lp);
                *(uint32_t*)(Oh + (size_t)r1 * DOUT + c0) = hp;
                *(uint32_t*)(Ol + (size_t)r1 * DOUT + c0) = lp;
            }
        }
    }
}

// ---------------- pool (binary-search graph bounds) + head -------------------
__global__ void k_pool(const unsigned short* __restrict__ Hh,
                       const unsigned short* __restrict__ Hl,
                       const int* __restrict__ batch) {
    __shared__ int ss, ee;
    int gidx = blockIdx.x, f = threadIdx.x;
    if (f == 0) {
        int lo = 0, hi = NN;
        while (lo < hi) { int m = (lo + hi) >> 1; if (batch[m] < gidx) lo = m + 1; else hi = m; }
        ss = lo;
        hi = NN;
        while (lo < hi) { int m = (lo + hi) >> 1; if (batch[m] < gidx + 1) lo = m + 1; else hi = m; }
        ee = lo;
    }
    __syncthreads();
    int s = ss, e = ee;
    float sum = 0.f;
    for (int n = s; n < e; n++) {
        size_t idx = (size_t)n * 256 + f;
        sum += __uint_as_float(((uint32_t)Hh[idx]) << 16)
             + __uint_as_float(((uint32_t)Hl[idx]) << 16);
    }
    int c = e - s; if (c < 1) c = 1;
    g_pool[gidx * 256 + f] = sum / (float)c;
}
__global__ void k_final(const float* __restrict__ Wlin, const float* __restrict__ blin,
                        float* __restrict__ out) {
    int idx = threadIdx.x;
    if (idx >= GG * 6) return;
    int g = idx / 6, o = idx % 6;
    float s = blin[o];
#pragma unroll 8
    for (int k = 0; k < 256; k++) s += g_pool[g * 256 + k] * Wlin[k * 6 + o];
    out[idx] = s;
}

// ---------------- launcher ----------------------------------------------------
extern "C" void kernel_launch(void* const* d_in, const int* in_sizes, int n_in,
                              void* d_out, int out_size) {
    const float* x     = (const float*)d_in[0];
    const int*   ei    = (const int*)d_in[1];
    const int*   batch = (const int*)d_in[2];
    WPtrs wp;
    const float* blp[6];
    for (int l = 0; l < 6; l++) {
        wp.w[2 * l]     = (const float*)d_in[3 + 3 * l];  // Wl
        blp[l]          = (const float*)d_in[4 + 3 * l];
        wp.w[2 * l + 1] = (const float*)d_in[5 + 3 * l];  // Wr
    }
    const float* Wlin = (const float*)d_in[21];
    const float* blin = (const float*)d_in[22];
    float* out = (float*)d_out;

    unsigned short *xh, *xl, *agh, *agl, *Ah, *Al, *Bh, *Bl, *wlh, *wll, *wrh, *wrl;
    cudaGetSymbolAddress((void**)&xh, g_xh);   cudaGetSymbolAddress((void**)&xl, g_xl);
    cudaGetSymbolAddress((void**)&agh, g_agh); cudaGetSymbolAddress((void**)&agl, g_agl);
    cudaGetSymbolAddress((void**)&Ah, g_Ah);   cudaGetSymbolAddress((void**)&Al, g_Al);
    cudaGetSymbolAddress((void**)&Bh, g_Bh);   cudaGetSymbolAddress((void**)&Bl, g_Bl);
    cudaGetSymbolAddress((void**)&wlh, g_wlh); cudaGetSymbolAddress((void**)&wll, g_wll);
    cudaGetSymbolAddress((void**)&wrh, g_wrh); cudaGetSymbolAddress((void**)&wrl, g_wrl);

    cudaFuncSetAttribute(k_gemm_tc<true>,  cudaFuncAttributeMaxDynamicSharedMemorySize, SMEM_BYTES);
    cudaFuncSetAttribute(k_gemm_tc<false>, cudaFuncAttributeMaxDynamicSharedMemorySize, SMEM_BYTES);

    const int din[6]  = {128, 256, 256, 512, 512, 256};
    const int dout[6] = {256, 256, 512, 512, 256, 256};
    const int woff[6] = {0, 32768, 98304, 229376, 491520, 622592};

    // setup: (1) convert  (2) count  (3) scan+reset  (4) fill
    k_cvtall<<<dim3(1250, 13), 256>>>(x, wp);
    k_count<<<(EE + 255) / 256, 256>>>(ei);
    k_scan<<<1, 1024>>>();
    k_fillcsr<<<(EE + 255) / 256, 256>>>(ei);

    const unsigned short* inh = xh; const unsigned short* inl = xl;
    for (int l = 0; l < 6; l++) {
        unsigned short* oh = (l & 1) ? Bh : Ah;
        unsigned short* ol = (l & 1) ? Bl : Al;
        dim3 agrid((NN + 7) / 8, din[l] >> 7);
        k_agg<<<agrid, 256>>>(inh, inl, agh, agl, din[l]);   // launch 5 (L1)
        dim3 grid(dout[l] / 128, (NN + 127) / 128);
        if (l < 5)
            k_gemm_tc<true><<<grid, 256, SMEM_BYTES>>>(       // launch 6 (L1) <- ncu
                agh, agl, inh, inl,
                wlh + woff[l], wll + woff[l], wrh + woff[l], wrl + woff[l],
                blp[l], oh, ol, din[l], dout[l]);
        else
            k_gemm_tc<false><<<grid, 256, SMEM_BYTES>>>(
                agh, agl, inh, inl,
                wlh + woff[l], wll + woff[l], wrh + woff[l], wrl + woff[l],
                blp[l], oh, ol, din[l], dout[l]);
        inh = oh; inl = ol;
    }
    k_pool<<<GG, 256>>>(inh, inl, batch);
    k_final<<<1, 384>>>(Wlin, blin, out);
}